// round 2
// baseline (speedup 1.0000x reference)
#include <cuda_runtime.h>
#include <stdint.h>

#define D_IN   256
#define D_HID  64
#define D_EMB  32
#define MAX_NODES 100000

typedef unsigned long long ull;

// Scratch (static __device__ — no allocation allowed)
__device__ float g_H [MAX_NODES * D_HID];   // x @ W1
__device__ float g_S1[MAX_NODES * D_HID];   // A @ H
__device__ float g_Z1[MAX_NODES * D_EMB];   // relu(S1+b1) @ W2
__device__ float g_S2[MAX_NODES * D_EMB];   // A @ Z1

// ---------------------------------------------------------------------------
// f32x2 packed math helpers (FFMA2 path — ptxas never emits from C++)
// ---------------------------------------------------------------------------
__device__ __forceinline__ ull fma2(ull a, ull b, ull c) {
    ull d;
    asm("fma.rn.f32x2 %0, %1, %2, %3;" : "=l"(d) : "l"(a), "l"(b), "l"(c));
    return d;
}
__device__ __forceinline__ ull pack2(float x, float y) {
    ull r;
    asm("mov.b64 %0, {%1, %2};" : "=l"(r) : "f"(x), "f"(y));
    return r;
}
__device__ __forceinline__ void unpack2(ull v, float& x, float& y) {
    asm("mov.b64 {%0, %1}, %2;" : "=f"(x), "=f"(y) : "l"(v));
}

// ---------------------------------------------------------------------------
// Zero the two scatter targets
// ---------------------------------------------------------------------------
__global__ void zero_kernel(int n64, int n32) {
    int i = blockIdx.x * blockDim.x + threadIdx.x;
    float4 z = make_float4(0.f, 0.f, 0.f, 0.f);
    int n64_4 = n64 >> 2;
    int n32_4 = n32 >> 2;
    if (i < n64_4) ((float4*)g_S1)[i] = z;
    if (i < n32_4) ((float4*)g_S2)[i] = z;
}

// ---------------------------------------------------------------------------
// GEMM1: H = x @ W1   [n,256] @ [256,64]
// Block tile 128x64, k-chunks of 32, 256 threads.
// Thread tile: 8 rows (4 row-pairs packed f32x2) x 4 cols -> 16 f32x2 accums.
// b is pre-broadcast-packed into shared (wsp[k][c] = {w,w}).
// ---------------------------------------------------------------------------
__global__ __launch_bounds__(256) void gemm1_kernel(
    const float* __restrict__ x, const float* __restrict__ W1, int n)
{
    __shared__ float xs[128][33];     // [row][k], stride 33 -> conflict-free
    __shared__ ull   wsp[32][64];     // [k][col] broadcast-packed W1 chunk

    int tid = threadIdx.x;
    int ty = tid >> 4;                // 0..15 -> rows ty*8 .. ty*8+7
    int tx = tid & 15;                // 0..15 -> cols tx*4 .. tx*4+3
    int row_base = blockIdx.x * 128;

    ull acc[4][4];
    #pragma unroll
    for (int p = 0; p < 4; p++)
        #pragma unroll
        for (int c = 0; c < 4; c++) acc[p][c] = 0ull;

    for (int kc = 0; kc < D_IN; kc += 32) {
        // load x tile: 128 rows x 32 k = 1024 float4, 4 per thread
        #pragma unroll
        for (int l = 0; l < 4; l++) {
            int flat = tid + l * 256;     // float4 index
            int r    = flat >> 3;         // 8 float4 per row
            int c4   = flat & 7;
            float4 v = make_float4(0.f, 0.f, 0.f, 0.f);
            int grow = row_base + r;
            if (grow < n)
                v = *(const float4*)(x + (size_t)grow * D_IN + kc + c4 * 4);
            xs[r][c4*4+0] = v.x; xs[r][c4*4+1] = v.y;
            xs[r][c4*4+2] = v.z; xs[r][c4*4+3] = v.w;
        }
        // load W1 chunk (32 k-rows x 64 cols), pack broadcast pairs
        #pragma unroll
        for (int l = 0; l < 2; l++) {
            int flat = tid + l * 256;     // float4 index, 512 total
            float4 w = *(const float4*)(W1 + (size_t)kc * 64 + (size_t)flat * 4);
            int k = flat >> 4;            // 16 float4 per k-row
            int c = (flat & 15) * 4;
            wsp[k][c+0] = pack2(w.x, w.x);
            wsp[k][c+1] = pack2(w.y, w.y);
            wsp[k][c+2] = pack2(w.z, w.z);
            wsp[k][c+3] = pack2(w.w, w.w);
        }
        __syncthreads();

        #pragma unroll
        for (int kk = 0; kk < 32; kk++) {
            // a: 8 scalar row values -> 4 row-pair f32x2
            ull a[4];
            #pragma unroll
            for (int p = 0; p < 4; p++)
                a[p] = pack2(xs[ty*8 + 2*p + 0][kk], xs[ty*8 + 2*p + 1][kk]);
            // b: 4 broadcast-packed cols (two 16B LDS)
            const ulonglong2* bp = (const ulonglong2*)&wsp[kk][tx*4];
            ulonglong2 b01 = bp[0];
            ulonglong2 b23 = bp[1];
            #pragma unroll
            for (int p = 0; p < 4; p++) {
                acc[p][0] = fma2(a[p], b01.x, acc[p][0]);
                acc[p][1] = fma2(a[p], b01.y, acc[p][1]);
                acc[p][2] = fma2(a[p], b23.x, acc[p][2]);
                acc[p][3] = fma2(a[p], b23.y, acc[p][3]);
            }
        }
        __syncthreads();
    }

    // epilogue: unpack and store
    int col = tx * 4;
    #pragma unroll
    for (int p = 0; p < 4; p++) {
        float lo[4], hi[4];
        #pragma unroll
        for (int c = 0; c < 4; c++) unpack2(acc[p][c], lo[c], hi[c]);
        int r0 = row_base + ty*8 + 2*p;
        if (r0 + 0 < n)
            *(float4*)(g_H + (size_t)(r0+0) * D_HID + col) =
                make_float4(lo[0], lo[1], lo[2], lo[3]);
        if (r0 + 1 < n)
            *(float4*)(g_H + (size_t)(r0+1) * D_HID + col) =
                make_float4(hi[0], hi[1], hi[2], hi[3]);
    }
}

// ---------------------------------------------------------------------------
// SpMM d=64: S1[dst] += val * H[src]. 16 threads per edge, float4 + red.v4.
// ---------------------------------------------------------------------------
__device__ __forceinline__ void red_add_v4(float* p, float4 v) {
    asm volatile("red.global.add.v4.f32 [%0], {%1,%2,%3,%4};"
                 :: "l"(p), "f"(v.x), "f"(v.y), "f"(v.z), "f"(v.w)
                 : "memory");
}

__global__ __launch_bounds__(256) void spmm64_kernel(
    const int* __restrict__ src, const int* __restrict__ dst,
    const float* __restrict__ val, int nnz)
{
    int t = blockIdx.x * blockDim.x + threadIdx.x;
    int e = t >> 4;
    int c = t & 15;
    if (e >= nnz) return;
    int   s = __ldg(src + e);
    int   d = __ldg(dst + e);
    float v = __ldg(val + e);
    float4 h = __ldg((const float4*)(g_H + (size_t)s * D_HID) + c);
    red_add_v4(g_S1 + (size_t)d * D_HID + c * 4,
               make_float4(v*h.x, v*h.y, v*h.z, v*h.w));
}

// ---------------------------------------------------------------------------
// GEMM2: Z1 = relu(S1 + b1) @ W2   [n,64] @ [64,32]
// Thread per row; z row in registers; 16 f32x2 accumulators over col-pairs.
// ---------------------------------------------------------------------------
__global__ __launch_bounds__(256) void gemm2_kernel(
    const float* __restrict__ b1, const float* __restrict__ W2, int n)
{
    __shared__ float4 ws4[64 * 8];    // W2: 64 k-rows x 32 cols = 512 float4

    int tid = threadIdx.x;
    // load W2
    #pragma unroll
    for (int l = 0; l < 2; l++) {
        int flat = tid + l * 256;
        ws4[flat] = __ldg((const float4*)W2 + flat);
    }
    __syncthreads();

    int r = blockIdx.x * 256 + tid;
    if (r >= n) return;

    // load z row (relu(S1+b1)) into registers
    float z[64];
    #pragma unroll
    for (int j = 0; j < 16; j++) {
        float4 v  = *(const float4*)(g_S1 + (size_t)r * D_HID + j * 4);
        float4 bb = __ldg((const float4*)b1 + j);
        z[j*4+0] = fmaxf(v.x + bb.x, 0.f);
        z[j*4+1] = fmaxf(v.y + bb.y, 0.f);
        z[j*4+2] = fmaxf(v.z + bb.z, 0.f);
        z[j*4+3] = fmaxf(v.w + bb.w, 0.f);
    }

    ull acc[16];
    #pragma unroll
    for (int j = 0; j < 16; j++) acc[j] = 0ull;

    #pragma unroll 8
    for (int k = 0; k < 64; k++) {
        ull a2 = pack2(z[k], z[k]);
        #pragma unroll
        for (int q = 0; q < 8; q++) {
            float4 w = ws4[k*8 + q];
            acc[q*2+0] = fma2(a2, pack2(w.x, w.y), acc[q*2+0]);
            acc[q*2+1] = fma2(a2, pack2(w.z, w.w), acc[q*2+1]);
        }
    }

    #pragma unroll
    for (int q = 0; q < 8; q++) {
        float o0, o1, o2, o3;
        unpack2(acc[q*2+0], o0, o1);
        unpack2(acc[q*2+1], o2, o3);
        *(float4*)(g_Z1 + (size_t)r * D_EMB + q * 4) = make_float4(o0, o1, o2, o3);
    }
}

// ---------------------------------------------------------------------------
// SpMM d=32: S2[dst] += val * Z1[src]. 8 threads per edge.
// ---------------------------------------------------------------------------
__global__ __launch_bounds__(256) void spmm32_kernel(
    const int* __restrict__ src, const int* __restrict__ dst,
    const float* __restrict__ val, int nnz)
{
    int t = blockIdx.x * blockDim.x + threadIdx.x;
    int e = t >> 3;
    int c = t & 7;
    if (e >= nnz) return;
    int   s = __ldg(src + e);
    int   d = __ldg(dst + e);
    float v = __ldg(val + e);
    float4 h = __ldg((const float4*)(g_Z1 + (size_t)s * D_EMB) + c);
    red_add_v4(g_S2 + (size_t)d * D_EMB + c * 4,
               make_float4(v*h.x, v*h.y, v*h.z, v*h.w));
}

// ---------------------------------------------------------------------------
// Decoder: scores[e] = dot(S2[src]+b2, S2[dst]+b2), d=32. 8 threads/edge.
// ---------------------------------------------------------------------------
__global__ __launch_bounds__(256) void decoder_kernel(
    const int* __restrict__ edge_index, const float* __restrict__ b2,
    float* __restrict__ out, int ne)
{
    int t = blockIdx.x * blockDim.x + threadIdx.x;
    int e = t >> 3;
    int c = t & 7;
    bool active = (e < ne);
    int ec = active ? e : (ne - 1);    // clamp so all lanes participate in shfl

    int s = __ldg(edge_index + ec);
    int d = __ldg(edge_index + ne + ec);
    float4 bb = __ldg((const float4*)b2 + c);
    float4 a = __ldg((const float4*)(g_S2 + (size_t)s * D_EMB) + c);
    float4 b = __ldg((const float4*)(g_S2 + (size_t)d * D_EMB) + c);

    float p = (a.x + bb.x) * (b.x + bb.x)
            + (a.y + bb.y) * (b.y + bb.y)
            + (a.z + bb.z) * (b.z + bb.z)
            + (a.w + bb.w) * (b.w + bb.w);

    p += __shfl_xor_sync(0xFFFFFFFFu, p, 1);
    p += __shfl_xor_sync(0xFFFFFFFFu, p, 2);
    p += __shfl_xor_sync(0xFFFFFFFFu, p, 4);

    if (active && c == 0) out[e] = p;
}

// ---------------------------------------------------------------------------
extern "C" void kernel_launch(void* const* d_in, const int* in_sizes, int n_in,
                              void* d_out, int out_size)
{
    const float* x         = (const float*)d_in[0];
    const int*   adj_src   = (const int*)  d_in[1];
    const int*   adj_dst   = (const int*)  d_in[2];
    const float* adj_val   = (const float*)d_in[3];
    const int*   edge_idx  = (const int*)  d_in[4];
    const float* W1        = (const float*)d_in[5];
    const float* b1        = (const float*)d_in[6];
    const float* W2        = (const float*)d_in[7];
    const float* b2        = (const float*)d_in[8];
    float*       out       = (float*)d_out;

    int n   = in_sizes[0] / D_IN;     // nodes
    int nnz = in_sizes[3];            // adjacency nnz
    int ne  = in_sizes[4] / 2;        // edges to score
    (void)n_in; (void)out_size;

    // zero scatter targets
    {
        int n4 = (n * D_HID) >> 2;    // larger of the two
        int blocks = (n4 + 255) / 256;
        zero_kernel<<<blocks, 256>>>(n * D_HID, n * D_EMB);
    }
    // GEMM1 (f32x2 packed)
    gemm1_kernel<<<(n + 127) / 128, 256>>>(x, W1, n);
    // SpMM1 (d=64)
    {
        long long total = (long long)nnz * 16;
        int blocks = (int)((total + 255) / 256);
        spmm64_kernel<<<blocks, 256>>>(adj_src, adj_dst, adj_val, nnz);
    }
    // GEMM2 (fused relu + b1, f32x2 packed)
    gemm2_kernel<<<(n + 255) / 256, 256>>>(b1, W2, n);
    // SpMM2 (d=32)
    {
        long long total = (long long)nnz * 8;
        int blocks = (int)((total + 255) / 256);
        spmm32_kernel<<<blocks, 256>>>(adj_src, adj_dst, adj_val, nnz);
    }
    // Decoder
    {
        long long total = (long long)ne * 8;
        int blocks = (int)((total + 255) / 256);
        decoder_kernel<<<blocks, 256>>>(edge_idx, b2, out, ne);
    }
}

// round 3
// speedup vs baseline: 1.0055x; 1.0055x over previous
#include <cuda_runtime.h>
#include <stdint.h>

#define D_IN   256
#define D_HID  64
#define D_EMB  32
#define MAX_NODES 100000
#define MAX_NNZ   3200000

typedef unsigned long long ull;

// Scratch (static __device__ — no allocation allowed)
__device__ float g_H [MAX_NODES * D_HID];   // x @ W1
__device__ float g_S1[MAX_NODES * D_HID];   // A @ H
__device__ float g_Z1[MAX_NODES * D_EMB];   // relu(S1+b1) @ W2
__device__ float g_S2[MAX_NODES * D_EMB];   // A @ Z1

// CSR scratch
__device__ int g_counts  [MAX_NODES];
__device__ int g_rowstart[MAX_NODES + 1];
__device__ int g_cursor  [MAX_NODES];
__device__ ull g_edge    [MAX_NNZ];         // packed: hi32=val bits, lo32=src

// ---------------------------------------------------------------------------
// CSR build: zero counts -> histogram -> scan (+cursor init) -> scatter
// ---------------------------------------------------------------------------
__global__ void zero_counts_kernel(int n) {
    int i = blockIdx.x * blockDim.x + threadIdx.x;
    if (i < n) g_counts[i] = 0;
}

__global__ __launch_bounds__(256) void hist_kernel(
    const int* __restrict__ dst, int nnz)
{
    int e = blockIdx.x * blockDim.x + threadIdx.x;
    if (e < nnz) atomicAdd(&g_counts[dst[e]], 1);   // result unused -> RED
}

__global__ __launch_bounds__(1024) void scan_kernel(int n) {
    __shared__ int wsums[32];
    int tid  = threadIdx.x;
    int lane = tid & 31, wid = tid >> 5;
    int C  = (n + 1023) >> 10;
    int lo = tid * C;
    int hi = min(lo + C, n);

    int s = 0;
    for (int i = lo; i < hi; i++) s += g_counts[i];

    int v = s;
    #pragma unroll
    for (int d = 1; d < 32; d <<= 1) {
        int t = __shfl_up_sync(0xffffffffu, v, d);
        if (lane >= d) v += t;
    }
    if (lane == 31) wsums[wid] = v;
    __syncthreads();
    if (wid == 0) {
        int w = wsums[lane];
        #pragma unroll
        for (int d = 1; d < 32; d <<= 1) {
            int t = __shfl_up_sync(0xffffffffu, w, d);
            if (lane >= d) w += t;
        }
        wsums[lane] = w;
    }
    __syncthreads();

    int excl = v - s + (wid > 0 ? wsums[wid - 1] : 0);
    int run  = excl;
    for (int i = lo; i < hi; i++) {
        int c = g_counts[i];
        g_rowstart[i] = run;
        g_cursor[i]   = run;
        run += c;
    }
    if (tid == 0) g_rowstart[n] = wsums[31];
}

__global__ __launch_bounds__(256) void scatter_kernel(
    const int* __restrict__ src, const int* __restrict__ dst,
    const float* __restrict__ val, int nnz)
{
    int e = blockIdx.x * blockDim.x + threadIdx.x;
    if (e >= nnz) return;
    int   s = __ldg(src + e);
    int   d = __ldg(dst + e);
    float v = __ldg(val + e);
    int pos = atomicAdd(&g_cursor[d], 1);
    g_edge[pos] = ((ull)__float_as_uint(v) << 32) | (unsigned)s;
}

// ---------------------------------------------------------------------------
// GEMM1: H = x @ W1   [n,256] @ [256,64]  (R1 version: 64x64 tile, 4x4 thr)
// ---------------------------------------------------------------------------
__global__ __launch_bounds__(256) void gemm1_kernel(
    const float* __restrict__ x, const float* __restrict__ W1, int n)
{
    __shared__ float xs[64][65];
    __shared__ float ws[64][64];

    int tid = threadIdx.x;
    int ty = tid >> 4;
    int tx = tid & 15;
    int row_base = blockIdx.x * 64;

    float acc00=0,acc01=0,acc02=0,acc03=0;
    float acc10=0,acc11=0,acc12=0,acc13=0;
    float acc20=0,acc21=0,acc22=0,acc23=0;
    float acc30=0,acc31=0,acc32=0,acc33=0;

    for (int kc = 0; kc < D_IN; kc += 64) {
        #pragma unroll
        for (int l = 0; l < 4; l++) {
            int flat = tid + l * 256;
            int r    = flat >> 4;
            int c4   = flat & 15;
            float4 v = make_float4(0.f,0.f,0.f,0.f);
            int grow = row_base + r;
            if (grow < n)
                v = *(const float4*)(x + (size_t)grow * D_IN + kc + c4 * 4);
            xs[r][c4*4+0] = v.x; xs[r][c4*4+1] = v.y;
            xs[r][c4*4+2] = v.z; xs[r][c4*4+3] = v.w;
        }
        #pragma unroll
        for (int l = 0; l < 4; l++) {
            int flat = tid + l * 256;
            ((float4*)&ws[0][0])[flat] =
                *(const float4*)(W1 + (size_t)kc * 64 + (size_t)flat * 4);
        }
        __syncthreads();

        #pragma unroll 16
        for (int kk = 0; kk < 64; kk++) {
            float a0 = xs[ty*4+0][kk];
            float a1 = xs[ty*4+1][kk];
            float a2 = xs[ty*4+2][kk];
            float a3 = xs[ty*4+3][kk];
            float4 b = *(float4*)&ws[kk][tx*4];
            acc00 += a0*b.x; acc01 += a0*b.y; acc02 += a0*b.z; acc03 += a0*b.w;
            acc10 += a1*b.x; acc11 += a1*b.y; acc12 += a1*b.z; acc13 += a1*b.w;
            acc20 += a2*b.x; acc21 += a2*b.y; acc22 += a2*b.z; acc23 += a2*b.w;
            acc30 += a3*b.x; acc31 += a3*b.y; acc32 += a3*b.z; acc33 += a3*b.w;
        }
        __syncthreads();
    }

    int col = tx * 4;
    int r0 = row_base + ty*4;
    if (r0 + 0 < n) *(float4*)(g_H + (size_t)(r0+0)*D_HID + col) = make_float4(acc00,acc01,acc02,acc03);
    if (r0 + 1 < n) *(float4*)(g_H + (size_t)(r0+1)*D_HID + col) = make_float4(acc10,acc11,acc12,acc13);
    if (r0 + 2 < n) *(float4*)(g_H + (size_t)(r0+2)*D_HID + col) = make_float4(acc20,acc21,acc22,acc23);
    if (r0 + 3 < n) *(float4*)(g_H + (size_t)(r0+3)*D_HID + col) = make_float4(acc30,acc31,acc32,acc33);
}

// ---------------------------------------------------------------------------
// SpMM (CSR, d=64): warp per dst row, lane owns float2 channel pair.
// ---------------------------------------------------------------------------
__global__ __launch_bounds__(256) void spmm64_csr_kernel(int n)
{
    __shared__ ull se[8][32];
    int wid  = threadIdx.x >> 5;
    int lane = threadIdx.x & 31;
    int row  = blockIdx.x * 8 + wid;
    if (row >= n) return;

    int start = g_rowstart[row];
    int end   = g_rowstart[row + 1];
    float2 acc = make_float2(0.f, 0.f);
    const float2* __restrict__ Hp = (const float2*)g_H;

    for (int base = start; base < end; base += 32) {
        int i = base + lane;
        se[wid][lane] = (i < end) ? __ldg(g_edge + i) : 0ull;
        __syncwarp();
        int cnt = min(32, end - base);
        for (int j = 0; j < cnt; j++) {
            ull p   = se[wid][j];
            int s   = (int)(unsigned)(p & 0xffffffffu);
            float v = __uint_as_float((unsigned)(p >> 32));
            float2 h = __ldg(Hp + (size_t)s * 32 + lane);
            acc.x += v * h.x;
            acc.y += v * h.y;
        }
        __syncwarp();
    }
    ((float2*)g_S1)[(size_t)row * 32 + lane] = acc;
}

// ---------------------------------------------------------------------------
// GEMM2: Z1 = relu(S1 + b1) @ W2   (R1 version)
// ---------------------------------------------------------------------------
__global__ __launch_bounds__(256) void gemm2_kernel(
    const float* __restrict__ b1, const float* __restrict__ W2, int n)
{
    __shared__ float zs[64][65];
    __shared__ float ws[64][32];

    int tid = threadIdx.x;
    int row_base = blockIdx.x * 64;

    #pragma unroll
    for (int l = 0; l < 4; l++) {
        int flat = tid + l * 256;
        int r  = flat >> 4;
        int c4 = flat & 15;
        float4 v = make_float4(0.f,0.f,0.f,0.f);
        if (row_base + r < n)
            v = *(const float4*)(g_S1 + (size_t)row_base * D_HID + (size_t)flat * 4);
        float4 bb = __ldg((const float4*)b1 + c4);
        v.x = fmaxf(v.x + bb.x, 0.f);
        v.y = fmaxf(v.y + bb.y, 0.f);
        v.z = fmaxf(v.z + bb.z, 0.f);
        v.w = fmaxf(v.w + bb.w, 0.f);
        zs[r][c4*4+0] = v.x; zs[r][c4*4+1] = v.y;
        zs[r][c4*4+2] = v.z; zs[r][c4*4+3] = v.w;
    }
    #pragma unroll
    for (int l = 0; l < 2; l++) {
        int flat = tid + l * 256;
        ((float4*)&ws[0][0])[flat] = __ldg((const float4*)W2 + flat);
    }
    __syncthreads();

    int ty = tid >> 3;
    int tx = tid & 7;
    int col = tx * 4;

    float a00=0,a01=0,a02=0,a03=0;
    float a10=0,a11=0,a12=0,a13=0;

    #pragma unroll 16
    for (int kk = 0; kk < 64; kk++) {
        float z0 = zs[ty*2+0][kk];
        float z1 = zs[ty*2+1][kk];
        float4 b = *(float4*)&ws[kk][col];
        a00 += z0*b.x; a01 += z0*b.y; a02 += z0*b.z; a03 += z0*b.w;
        a10 += z1*b.x; a11 += z1*b.y; a12 += z1*b.z; a13 += z1*b.w;
    }

    int r0 = row_base + ty*2;
    if (r0 + 0 < n) *(float4*)(g_Z1 + (size_t)(r0+0)*D_EMB + col) = make_float4(a00,a01,a02,a03);
    if (r0 + 1 < n) *(float4*)(g_Z1 + (size_t)(r0+1)*D_EMB + col) = make_float4(a10,a11,a12,a13);
}

// ---------------------------------------------------------------------------
// SpMM (CSR, d=32): warp per dst row, lane owns one channel.
// ---------------------------------------------------------------------------
__global__ __launch_bounds__(256) void spmm32_csr_kernel(int n)
{
    __shared__ ull se[8][32];
    int wid  = threadIdx.x >> 5;
    int lane = threadIdx.x & 31;
    int row  = blockIdx.x * 8 + wid;
    if (row >= n) return;

    int start = g_rowstart[row];
    int end   = g_rowstart[row + 1];
    float acc = 0.f;

    for (int base = start; base < end; base += 32) {
        int i = base + lane;
        se[wid][lane] = (i < end) ? __ldg(g_edge + i) : 0ull;
        __syncwarp();
        int cnt = min(32, end - base);
        for (int j = 0; j < cnt; j++) {
            ull p   = se[wid][j];
            int s   = (int)(unsigned)(p & 0xffffffffu);
            float v = __uint_as_float((unsigned)(p >> 32));
            float h = __ldg(g_Z1 + (size_t)s * D_EMB + lane);
            acc += v * h;
        }
        __syncwarp();
    }
    g_S2[(size_t)row * D_EMB + lane] = acc;
}

// ---------------------------------------------------------------------------
// Decoder: scores[e] = dot(S2[src]+b2, S2[dst]+b2), d=32. 8 threads/edge.
// ---------------------------------------------------------------------------
__global__ __launch_bounds__(256) void decoder_kernel(
    const int* __restrict__ edge_index, const float* __restrict__ b2,
    float* __restrict__ out, int ne)
{
    int t = blockIdx.x * blockDim.x + threadIdx.x;
    int e = t >> 3;
    int c = t & 7;
    bool active = (e < ne);
    int ec = active ? e : (ne - 1);

    int s = __ldg(edge_index + ec);
    int d = __ldg(edge_index + ne + ec);
    float4 bb = __ldg((const float4*)b2 + c);
    float4 a = __ldg((const float4*)(g_S2 + (size_t)s * D_EMB) + c);
    float4 b = __ldg((const float4*)(g_S2 + (size_t)d * D_EMB) + c);

    float p = (a.x + bb.x) * (b.x + bb.x)
            + (a.y + bb.y) * (b.y + bb.y)
            + (a.z + bb.z) * (b.z + bb.z)
            + (a.w + bb.w) * (b.w + bb.w);

    p += __shfl_xor_sync(0xFFFFFFFFu, p, 1);
    p += __shfl_xor_sync(0xFFFFFFFFu, p, 2);
    p += __shfl_xor_sync(0xFFFFFFFFu, p, 4);

    if (active && c == 0) out[e] = p;
}

// ---------------------------------------------------------------------------
extern "C" void kernel_launch(void* const* d_in, const int* in_sizes, int n_in,
                              void* d_out, int out_size)
{
    const float* x         = (const float*)d_in[0];
    const int*   adj_src   = (const int*)  d_in[1];
    const int*   adj_dst   = (const int*)  d_in[2];
    const float* adj_val   = (const float*)d_in[3];
    const int*   edge_idx  = (const int*)  d_in[4];
    const float* W1        = (const float*)d_in[5];
    const float* b1        = (const float*)d_in[6];
    const float* W2        = (const float*)d_in[7];
    const float* b2        = (const float*)d_in[8];
    float*       out       = (float*)d_out;

    int n   = in_sizes[0] / D_IN;
    int nnz = in_sizes[3];
    int ne  = in_sizes[4] / 2;
    (void)n_in; (void)out_size;

    // --- CSR build ---
    zero_counts_kernel<<<(n + 255) / 256, 256>>>(n);
    hist_kernel<<<(nnz + 255) / 256, 256>>>(adj_dst, nnz);
    scan_kernel<<<1, 1024>>>(n);
    scatter_kernel<<<(nnz + 255) / 256, 256>>>(adj_src, adj_dst, adj_val, nnz);

    // --- GNN pipeline ---
    gemm1_kernel<<<(n + 63) / 64, 256>>>(x, W1, n);
    spmm64_csr_kernel<<<(n + 7) / 8, 256>>>(n);
    gemm2_kernel<<<(n + 63) / 64, 256>>>(b1, W2, n);
    spmm32_csr_kernel<<<(n + 7) / 8, 256>>>(n);

    // --- Decoder ---
    {
        long long total = (long long)ne * 8;
        int blocks = (int)((total + 255) / 256);
        decoder_kernel<<<blocks, 256>>>(edge_idx, b2, out, ne);
    }
}

// round 4
// speedup vs baseline: 1.1869x; 1.1805x over previous
#include <cuda_runtime.h>
#include <stdint.h>

#define D_IN   256
#define D_HID  64
#define D_EMB  32
#define MAX_NODES 100000

// Scratch (static __device__ — no allocation allowed)
__device__ float g_H [MAX_NODES * D_HID];   // x @ W1
__device__ float g_S1[MAX_NODES * D_HID];   // A @ H
__device__ float g_Z1[MAX_NODES * D_EMB];   // relu(S1+b1) @ W2
__device__ float g_S2[MAX_NODES * D_EMB];   // A @ Z1

// ---------------------------------------------------------------------------
// Zero the two scatter targets
// ---------------------------------------------------------------------------
__global__ void zero_kernel(int n64, int n32) {
    int i = blockIdx.x * blockDim.x + threadIdx.x;
    float4 z = make_float4(0.f, 0.f, 0.f, 0.f);
    int n64_4 = n64 >> 2;
    int n32_4 = n32 >> 2;
    if (i < n64_4) ((float4*)g_S1)[i] = z;
    if (i < n32_4) ((float4*)g_S2)[i] = z;
}

// ---------------------------------------------------------------------------
// TF32 helpers
// ---------------------------------------------------------------------------
__device__ __forceinline__ unsigned f2tf32(float f) {
    unsigned r;
    asm("cvt.rna.tf32.f32 %0, %1;" : "=r"(r) : "f"(f));
    return r;
}

__device__ __forceinline__ void mma_tf32(
    float& d0, float& d1, float& d2, float& d3,
    unsigned a0, unsigned a1, unsigned a2, unsigned a3,
    unsigned b0, unsigned b1)
{
    asm volatile(
        "mma.sync.aligned.m16n8k8.row.col.f32.tf32.tf32.f32 "
        "{%0,%1,%2,%3}, {%4,%5,%6,%7}, {%8,%9}, {%0,%1,%2,%3};"
        : "+f"(d0), "+f"(d1), "+f"(d2), "+f"(d3)
        : "r"(a0), "r"(a1), "r"(a2), "r"(a3), "r"(b0), "r"(b1));
}

// ---------------------------------------------------------------------------
// GEMM1 (TF32 tensor core): H = x @ W1   [n,256] @ [256,64]
// 256 threads = 8 warps. Block tile 128x64 (warp tile 16x64).
// K-chunks of 32; mma.m16n8k8, frags via padded smem (conflict-free).
// ---------------------------------------------------------------------------
__global__ __launch_bounds__(256) void gemm1_tf32_kernel(
    const float* __restrict__ x, const float* __restrict__ W1, int n)
{
    __shared__ unsigned xs[128][36];   // [row][k] stride 36 -> a-frag conflict-free
    __shared__ unsigned ws[32][72];    // [k][col] stride 72 -> b-frag conflict-free

    int tid  = threadIdx.x;
    int warp = tid >> 5;
    int lane = tid & 31;
    int row_base = blockIdx.x * 128;
    int wm = warp * 16;

    float c[8][4];
    #pragma unroll
    for (int nt = 0; nt < 8; nt++)
        #pragma unroll
        for (int i = 0; i < 4; i++) c[nt][i] = 0.f;

    int qrow = lane >> 2;     // 0..7
    int qcol = lane & 3;      // 0..3

    for (int kc = 0; kc < D_IN; kc += 32) {
        // fill xs: 128 rows x 32 k = 1024 float4
        #pragma unroll
        for (int l = 0; l < 4; l++) {
            int flat = tid + l * 256;   // float4 index
            int r    = flat >> 3;       // 8 float4 per row
            int c4   = flat & 7;
            float4 v = make_float4(0.f, 0.f, 0.f, 0.f);
            int grow = row_base + r;
            if (grow < n)
                v = *(const float4*)(x + (size_t)grow * D_IN + kc + c4 * 4);
            xs[r][c4*4+0] = f2tf32(v.x);
            xs[r][c4*4+1] = f2tf32(v.y);
            xs[r][c4*4+2] = f2tf32(v.z);
            xs[r][c4*4+3] = f2tf32(v.w);
        }
        // fill ws: 32 k-rows x 64 cols = 512 float4
        #pragma unroll
        for (int l = 0; l < 2; l++) {
            int flat = tid + l * 256;
            int k  = flat >> 4;         // 16 float4 per k-row
            int cc = (flat & 15) * 4;
            float4 w = *(const float4*)(W1 + (size_t)(kc + k) * 64 + cc);
            ws[k][cc+0] = f2tf32(w.x);
            ws[k][cc+1] = f2tf32(w.y);
            ws[k][cc+2] = f2tf32(w.z);
            ws[k][cc+3] = f2tf32(w.w);
        }
        __syncthreads();

        #pragma unroll
        for (int k8 = 0; k8 < 4; k8++) {
            int ar = wm + qrow;
            int ac = k8 * 8 + qcol;
            unsigned a0 = xs[ar    ][ac    ];
            unsigned a1 = xs[ar + 8][ac    ];
            unsigned a2 = xs[ar    ][ac + 4];
            unsigned a3 = xs[ar + 8][ac + 4];
            #pragma unroll
            for (int nt = 0; nt < 8; nt++) {
                unsigned b0 = ws[k8*8 + qcol    ][nt*8 + qrow];
                unsigned b1 = ws[k8*8 + qcol + 4][nt*8 + qrow];
                mma_tf32(c[nt][0], c[nt][1], c[nt][2], c[nt][3],
                         a0, a1, a2, a3, b0, b1);
            }
        }
        __syncthreads();
    }

    // epilogue: c0,c1 -> (row, 2q..2q+1), c2,c3 -> (row+8, ...)
    int r0 = row_base + wm + qrow;
    int cb = qcol * 2;
    #pragma unroll
    for (int nt = 0; nt < 8; nt++) {
        if (r0 < n)
            *(float2*)(g_H + (size_t)r0 * D_HID + nt*8 + cb) =
                make_float2(c[nt][0], c[nt][1]);
        if (r0 + 8 < n)
            *(float2*)(g_H + (size_t)(r0 + 8) * D_HID + nt*8 + cb) =
                make_float2(c[nt][2], c[nt][3]);
    }
}

// ---------------------------------------------------------------------------
// SpMM d=64: S1[dst] += val * H[src]. 16 threads per edge, float4 + red.v4.
// ---------------------------------------------------------------------------
__device__ __forceinline__ void red_add_v4(float* p, float4 v) {
    asm volatile("red.global.add.v4.f32 [%0], {%1,%2,%3,%4};"
                 :: "l"(p), "f"(v.x), "f"(v.y), "f"(v.z), "f"(v.w)
                 : "memory");
}

__global__ __launch_bounds__(256) void spmm64_kernel(
    const int* __restrict__ src, const int* __restrict__ dst,
    const float* __restrict__ val, int nnz)
{
    int t = blockIdx.x * blockDim.x + threadIdx.x;
    int e = t >> 4;
    int c = t & 15;
    if (e >= nnz) return;
    int   s = __ldg(src + e);
    int   d = __ldg(dst + e);
    float v = __ldg(val + e);
    float4 h = __ldg((const float4*)(g_H + (size_t)s * D_HID) + c);
    red_add_v4(g_S1 + (size_t)d * D_HID + c * 4,
               make_float4(v*h.x, v*h.y, v*h.z, v*h.w));
}

// ---------------------------------------------------------------------------
// GEMM2: Z1 = relu(S1 + b1) @ W2   [n,64] @ [64,32]
// ---------------------------------------------------------------------------
__global__ __launch_bounds__(256) void gemm2_kernel(
    const float* __restrict__ b1, const float* __restrict__ W2, int n)
{
    __shared__ float zs[64][65];
    __shared__ float ws[64][32];

    int tid = threadIdx.x;
    int row_base = blockIdx.x * 64;

    #pragma unroll
    for (int l = 0; l < 4; l++) {
        int flat = tid + l * 256;
        int r  = flat >> 4;
        int c4 = flat & 15;
        float4 v = make_float4(0.f,0.f,0.f,0.f);
        if (row_base + r < n)
            v = *(const float4*)(g_S1 + (size_t)row_base * D_HID + (size_t)flat * 4);
        float4 bb = __ldg((const float4*)b1 + c4);
        v.x = fmaxf(v.x + bb.x, 0.f);
        v.y = fmaxf(v.y + bb.y, 0.f);
        v.z = fmaxf(v.z + bb.z, 0.f);
        v.w = fmaxf(v.w + bb.w, 0.f);
        zs[r][c4*4+0] = v.x; zs[r][c4*4+1] = v.y;
        zs[r][c4*4+2] = v.z; zs[r][c4*4+3] = v.w;
    }
    #pragma unroll
    for (int l = 0; l < 2; l++) {
        int flat = tid + l * 256;
        ((float4*)&ws[0][0])[flat] = __ldg((const float4*)W2 + flat);
    }
    __syncthreads();

    int ty = tid >> 3;
    int tx = tid & 7;
    int col = tx * 4;

    float a00=0,a01=0,a02=0,a03=0;
    float a10=0,a11=0,a12=0,a13=0;

    #pragma unroll 16
    for (int kk = 0; kk < 64; kk++) {
        float z0 = zs[ty*2+0][kk];
        float z1 = zs[ty*2+1][kk];
        float4 b = *(float4*)&ws[kk][col];
        a00 += z0*b.x; a01 += z0*b.y; a02 += z0*b.z; a03 += z0*b.w;
        a10 += z1*b.x; a11 += z1*b.y; a12 += z1*b.z; a13 += z1*b.w;
    }

    int r0 = row_base + ty*2;
    if (r0 + 0 < n) *(float4*)(g_Z1 + (size_t)(r0+0)*D_EMB + col) = make_float4(a00,a01,a02,a03);
    if (r0 + 1 < n) *(float4*)(g_Z1 + (size_t)(r0+1)*D_EMB + col) = make_float4(a10,a11,a12,a13);
}

// ---------------------------------------------------------------------------
// SpMM d=32: S2[dst] += val * Z1[src]. 8 threads per edge.
// ---------------------------------------------------------------------------
__global__ __launch_bounds__(256) void spmm32_kernel(
    const int* __restrict__ src, const int* __restrict__ dst,
    const float* __restrict__ val, int nnz)
{
    int t = blockIdx.x * blockDim.x + threadIdx.x;
    int e = t >> 3;
    int c = t & 7;
    if (e >= nnz) return;
    int   s = __ldg(src + e);
    int   d = __ldg(dst + e);
    float v = __ldg(val + e);
    float4 h = __ldg((const float4*)(g_Z1 + (size_t)s * D_EMB) + c);
    red_add_v4(g_S2 + (size_t)d * D_EMB + c * 4,
               make_float4(v*h.x, v*h.y, v*h.z, v*h.w));
}

// ---------------------------------------------------------------------------
// Decoder: scores[e] = dot(S2[src]+b2, S2[dst]+b2), d=32. 8 threads/edge.
// ---------------------------------------------------------------------------
__global__ __launch_bounds__(256) void decoder_kernel(
    const int* __restrict__ edge_index, const float* __restrict__ b2,
    float* __restrict__ out, int ne)
{
    int t = blockIdx.x * blockDim.x + threadIdx.x;
    int e = t >> 3;
    int c = t & 7;
    bool active = (e < ne);
    int ec = active ? e : (ne - 1);

    int s = __ldg(edge_index + ec);
    int d = __ldg(edge_index + ne + ec);
    float4 bb = __ldg((const float4*)b2 + c);
    float4 a = __ldg((const float4*)(g_S2 + (size_t)s * D_EMB) + c);
    float4 b = __ldg((const float4*)(g_S2 + (size_t)d * D_EMB) + c);

    float p = (a.x + bb.x) * (b.x + bb.x)
            + (a.y + bb.y) * (b.y + bb.y)
            + (a.z + bb.z) * (b.z + bb.z)
            + (a.w + bb.w) * (b.w + bb.w);

    p += __shfl_xor_sync(0xFFFFFFFFu, p, 1);
    p += __shfl_xor_sync(0xFFFFFFFFu, p, 2);
    p += __shfl_xor_sync(0xFFFFFFFFu, p, 4);

    if (active && c == 0) out[e] = p;
}

// ---------------------------------------------------------------------------
extern "C" void kernel_launch(void* const* d_in, const int* in_sizes, int n_in,
                              void* d_out, int out_size)
{
    const float* x         = (const float*)d_in[0];
    const int*   adj_src   = (const int*)  d_in[1];
    const int*   adj_dst   = (const int*)  d_in[2];
    const float* adj_val   = (const float*)d_in[3];
    const int*   edge_idx  = (const int*)  d_in[4];
    const float* W1        = (const float*)d_in[5];
    const float* b1        = (const float*)d_in[6];
    const float* W2        = (const float*)d_in[7];
    const float* b2        = (const float*)d_in[8];
    float*       out       = (float*)d_out;

    int n   = in_sizes[0] / D_IN;
    int nnz = in_sizes[3];
    int ne  = in_sizes[4] / 2;
    (void)n_in; (void)out_size;

    // zero scatter targets
    {
        int n4 = (n * D_HID) >> 2;
        int blocks = (n4 + 255) / 256;
        zero_kernel<<<blocks, 256>>>(n * D_HID, n * D_EMB);
    }
    // GEMM1 (TF32 tensor core)
    gemm1_tf32_kernel<<<(n + 127) / 128, 256>>>(x, W1, n);
    // SpMM1 (d=64)
    {
        long long total = (long long)nnz * 16;
        int blocks = (int)((total + 255) / 256);
        spmm64_kernel<<<blocks, 256>>>(adj_src, adj_dst, adj_val, nnz);
    }
    // GEMM2 (fused relu + b1)
    gemm2_kernel<<<(n + 63) / 64, 256>>>(b1, W2, n);
    // SpMM2 (d=32)
    {
        long long total = (long long)nnz * 8;
        int blocks = (int)((total + 255) / 256);
        spmm32_kernel<<<blocks, 256>>>(adj_src, adj_dst, adj_val, nnz);
    }
    // Decoder
    {
        long long total = (long long)ne * 8;
        int blocks = (int)((total + 255) / 256);
        decoder_kernel<<<blocks, 256>>>(edge_idx, b2, out, ne);
    }
}

// round 5
// speedup vs baseline: 1.2715x; 1.0712x over previous
#include <cuda_runtime.h>
#include <stdint.h>

#define D_IN   256
#define D_HID  64
#define D_EMB  32
#define MAX_NODES 100000

// Scratch (static __device__ — no allocation allowed)
__device__ float g_H [MAX_NODES * D_HID];   // x @ W1
__device__ float g_S1[MAX_NODES * D_HID];   // A @ H
__device__ float g_Z1[MAX_NODES * D_EMB];   // relu(S1+b1) @ W2
__device__ float g_S2[MAX_NODES * D_EMB];   // A @ Z1

// ---------------------------------------------------------------------------
// TF32 helpers
// ---------------------------------------------------------------------------
__device__ __forceinline__ unsigned f2tf32(float f) {
    unsigned r;
    asm("cvt.rna.tf32.f32 %0, %1;" : "=r"(r) : "f"(f));
    return r;
}

__device__ __forceinline__ void mma_tf32(
    float& d0, float& d1, float& d2, float& d3,
    unsigned a0, unsigned a1, unsigned a2, unsigned a3,
    unsigned b0, unsigned b1)
{
    asm volatile(
        "mma.sync.aligned.m16n8k8.row.col.f32.tf32.tf32.f32 "
        "{%0,%1,%2,%3}, {%4,%5,%6,%7}, {%8,%9}, {%0,%1,%2,%3};"
        : "+f"(d0), "+f"(d1), "+f"(d2), "+f"(d3)
        : "r"(a0), "r"(a1), "r"(a2), "r"(a3), "r"(b0), "r"(b1));
}

__device__ __forceinline__ void cp_async16(unsigned smem_addr, const void* gptr) {
    asm volatile("cp.async.cg.shared.global [%0], [%1], 16;"
                 :: "r"(smem_addr), "l"(gptr));
}

// ---------------------------------------------------------------------------
// GEMM1 (TF32 + cp.async double buffer + fused zeroing)
//   H = x @ W1   [n,256] @ [256,64]
// 256 threads = 8 warps, block tile 128x64 (warp tile 16x64).
// Dynamic smem: W1 full (tf32) [256][72] + x raw fp32 [2][128][36].
// ---------------------------------------------------------------------------
#define W_STRIDE 72
#define X_STRIDE 36
#define W_WORDS  (256 * W_STRIDE)          // 18432
#define X_WORDS  (128 * X_STRIDE)          // 4608 per buffer
#define GEMM1_SMEM ((W_WORDS + 2 * X_WORDS) * 4)   // 110592 bytes

__global__ __launch_bounds__(256) void gemm1_tf32_v3(
    const float* __restrict__ x, const float* __restrict__ W1, int n)
{
    extern __shared__ unsigned smem[];
    unsigned* Wsh = smem;                  // [256][72]
    float*    xsf = (float*)(smem + W_WORDS);   // [2][128][36]

    int tid  = threadIdx.x;
    int warp = tid >> 5;
    int lane = tid & 31;
    int row_base = blockIdx.x * 128;
    int wm   = warp * 16;
    int qrow = lane >> 2;
    int qcol = lane & 3;

    unsigned xs_base;
    asm("{ .reg .u64 t; cvta.to.shared.u64 t, %1; cvt.u32.u64 %0, t; }"
        : "=r"(xs_base) : "l"(xsf));

    // ---- prefetch x chunk 0 into buffer 0 ----
    #pragma unroll
    for (int l = 0; l < 4; l++) {
        int flat = tid + l * 256;          // float4 index (1024 total)
        int r    = flat >> 3;
        int c4   = flat & 7;
        int grow = row_base + r; if (grow >= n) grow = n - 1;
        cp_async16(xs_base + (unsigned)(r * X_STRIDE + c4 * 4) * 4,
                   x + (size_t)grow * D_IN + c4 * 4);
    }
    asm volatile("cp.async.commit_group;");

    // ---- stage whole W1 (tf32) ----
    #pragma unroll
    for (int l = 0; l < 16; l++) {
        int flat = tid + l * 256;          // float4 index over 256x64 (4096)
        int k  = flat >> 4;
        int cc = (flat & 15) * 4;
        float4 w = __ldg((const float4*)(W1 + (size_t)k * 64 + cc));
        Wsh[k * W_STRIDE + cc + 0] = f2tf32(w.x);
        Wsh[k * W_STRIDE + cc + 1] = f2tf32(w.y);
        Wsh[k * W_STRIDE + cc + 2] = f2tf32(w.z);
        Wsh[k * W_STRIDE + cc + 3] = f2tf32(w.w);
    }

    // ---- fused zeroing of S1 / S2 (overlaps prefetch latency) ----
    {
        int gtid = blockIdx.x * 256 + tid;
        int nthr = gridDim.x * 256;
        float4 z = make_float4(0.f, 0.f, 0.f, 0.f);
        for (int i = gtid; i < n * 16; i += nthr) ((float4*)g_S1)[i] = z;
        for (int i = gtid; i < n * 8;  i += nthr) ((float4*)g_S2)[i] = z;
    }

    float c[8][4];
    #pragma unroll
    for (int nt = 0; nt < 8; nt++)
        #pragma unroll
        for (int i = 0; i < 4; i++) c[nt][i] = 0.f;

    // ---- main loop over 8 k-chunks of 32 ----
    #pragma unroll
    for (int kc = 0; kc < 8; kc++) {
        if (kc + 1 < 8) {
            int buf = (kc + 1) & 1;
            #pragma unroll
            for (int l = 0; l < 4; l++) {
                int flat = tid + l * 256;
                int r    = flat >> 3;
                int c4   = flat & 7;
                int grow = row_base + r; if (grow >= n) grow = n - 1;
                cp_async16(xs_base + (unsigned)(buf * X_WORDS + r * X_STRIDE + c4 * 4) * 4,
                           x + (size_t)grow * D_IN + (kc + 1) * 32 + c4 * 4);
            }
            asm volatile("cp.async.commit_group;");
            asm volatile("cp.async.wait_group 1;");
        } else {
            asm volatile("cp.async.wait_group 0;");
        }
        __syncthreads();

        const unsigned* xb = (const unsigned*)(xsf + (kc & 1) * X_WORDS);
        #pragma unroll
        for (int k8 = 0; k8 < 4; k8++) {
            int ar = wm + qrow;
            int ac = k8 * 8 + qcol;
            unsigned a0 = xb[(ar    ) * X_STRIDE + ac    ];
            unsigned a1 = xb[(ar + 8) * X_STRIDE + ac    ];
            unsigned a2 = xb[(ar    ) * X_STRIDE + ac + 4];
            unsigned a3 = xb[(ar + 8) * X_STRIDE + ac + 4];
            int kg = kc * 32 + k8 * 8 + qcol;
            #pragma unroll
            for (int nt = 0; nt < 8; nt++) {
                unsigned b0 = Wsh[(kg    ) * W_STRIDE + nt * 8 + qrow];
                unsigned b1 = Wsh[(kg + 4) * W_STRIDE + nt * 8 + qrow];
                mma_tf32(c[nt][0], c[nt][1], c[nt][2], c[nt][3],
                         a0, a1, a2, a3, b0, b1);
            }
        }
        __syncthreads();
    }

    // ---- epilogue ----
    int r0 = row_base + wm + qrow;
    int cb = qcol * 2;
    #pragma unroll
    for (int nt = 0; nt < 8; nt++) {
        if (r0 < n)
            *(float2*)(g_H + (size_t)r0 * D_HID + nt*8 + cb) =
                make_float2(c[nt][0], c[nt][1]);
        if (r0 + 8 < n)
            *(float2*)(g_H + (size_t)(r0 + 8) * D_HID + nt*8 + cb) =
                make_float2(c[nt][2], c[nt][3]);
    }
}

// ---------------------------------------------------------------------------
// SpMM d=64: S1[dst] += val * H[src]. 16 threads per edge, float4 + red.v4.
// ---------------------------------------------------------------------------
__device__ __forceinline__ void red_add_v4(float* p, float4 v) {
    asm volatile("red.global.add.v4.f32 [%0], {%1,%2,%3,%4};"
                 :: "l"(p), "f"(v.x), "f"(v.y), "f"(v.z), "f"(v.w)
                 : "memory");
}

__global__ __launch_bounds__(256) void spmm64_kernel(
    const int* __restrict__ src, const int* __restrict__ dst,
    const float* __restrict__ val, int nnz)
{
    int t = blockIdx.x * blockDim.x + threadIdx.x;
    int e = t >> 4;
    int c = t & 15;
    if (e >= nnz) return;
    int   s = __ldg(src + e);
    int   d = __ldg(dst + e);
    float v = __ldg(val + e);
    float4 h = __ldg((const float4*)(g_H + (size_t)s * D_HID) + c);
    red_add_v4(g_S1 + (size_t)d * D_HID + c * 4,
               make_float4(v*h.x, v*h.y, v*h.z, v*h.w));
}

// ---------------------------------------------------------------------------
// GEMM2: Z1 = relu(S1 + b1) @ W2   [n,64] @ [64,32]
// ---------------------------------------------------------------------------
__global__ __launch_bounds__(256) void gemm2_kernel(
    const float* __restrict__ b1, const float* __restrict__ W2, int n)
{
    __shared__ float zs[64][65];
    __shared__ float ws[64][32];

    int tid = threadIdx.x;
    int row_base = blockIdx.x * 64;

    #pragma unroll
    for (int l = 0; l < 4; l++) {
        int flat = tid + l * 256;
        int r  = flat >> 4;
        int c4 = flat & 15;
        float4 v = make_float4(0.f,0.f,0.f,0.f);
        if (row_base + r < n)
            v = *(const float4*)(g_S1 + (size_t)row_base * D_HID + (size_t)flat * 4);
        float4 bb = __ldg((const float4*)b1 + c4);
        v.x = fmaxf(v.x + bb.x, 0.f);
        v.y = fmaxf(v.y + bb.y, 0.f);
        v.z = fmaxf(v.z + bb.z, 0.f);
        v.w = fmaxf(v.w + bb.w, 0.f);
        zs[r][c4*4+0] = v.x; zs[r][c4*4+1] = v.y;
        zs[r][c4*4+2] = v.z; zs[r][c4*4+3] = v.w;
    }
    #pragma unroll
    for (int l = 0; l < 2; l++) {
        int flat = tid + l * 256;
        ((float4*)&ws[0][0])[flat] = __ldg((const float4*)W2 + flat);
    }
    __syncthreads();

    int ty = tid >> 3;
    int tx = tid & 7;
    int col = tx * 4;

    float a00=0,a01=0,a02=0,a03=0;
    float a10=0,a11=0,a12=0,a13=0;

    #pragma unroll 16
    for (int kk = 0; kk < 64; kk++) {
        float z0 = zs[ty*2+0][kk];
        float z1 = zs[ty*2+1][kk];
        float4 b = *(float4*)&ws[kk][col];
        a00 += z0*b.x; a01 += z0*b.y; a02 += z0*b.z; a03 += z0*b.w;
        a10 += z1*b.x; a11 += z1*b.y; a12 += z1*b.z; a13 += z1*b.w;
    }

    int r0 = row_base + ty*2;
    if (r0 + 0 < n) *(float4*)(g_Z1 + (size_t)(r0+0)*D_EMB + col) = make_float4(a00,a01,a02,a03);
    if (r0 + 1 < n) *(float4*)(g_Z1 + (size_t)(r0+1)*D_EMB + col) = make_float4(a10,a11,a12,a13);
}

// ---------------------------------------------------------------------------
// SpMM d=32: S2[dst] += val * Z1[src]. 8 threads per edge.
// ---------------------------------------------------------------------------
__global__ __launch_bounds__(256) void spmm32_kernel(
    const int* __restrict__ src, const int* __restrict__ dst,
    const float* __restrict__ val, int nnz)
{
    int t = blockIdx.x * blockDim.x + threadIdx.x;
    int e = t >> 3;
    int c = t & 7;
    if (e >= nnz) return;
    int   s = __ldg(src + e);
    int   d = __ldg(dst + e);
    float v = __ldg(val + e);
    float4 h = __ldg((const float4*)(g_Z1 + (size_t)s * D_EMB) + c);
    red_add_v4(g_S2 + (size_t)d * D_EMB + c * 4,
               make_float4(v*h.x, v*h.y, v*h.z, v*h.w));
}

// ---------------------------------------------------------------------------
// Decoder: scores[e] = dot(S2[src]+b2, S2[dst]+b2), d=32. 8 threads/edge.
// ---------------------------------------------------------------------------
__global__ __launch_bounds__(256) void decoder_kernel(
    const int* __restrict__ edge_index, const float* __restrict__ b2,
    float* __restrict__ out, int ne)
{
    int t = blockIdx.x * blockDim.x + threadIdx.x;
    int e = t >> 3;
    int c = t & 7;
    bool active = (e < ne);
    int ec = active ? e : (ne - 1);

    int s = __ldg(edge_index + ec);
    int d = __ldg(edge_index + ne + ec);
    float4 bb = __ldg((const float4*)b2 + c);
    float4 a = __ldg((const float4*)(g_S2 + (size_t)s * D_EMB) + c);
    float4 b = __ldg((const float4*)(g_S2 + (size_t)d * D_EMB) + c);

    float p = (a.x + bb.x) * (b.x + bb.x)
            + (a.y + bb.y) * (b.y + bb.y)
            + (a.z + bb.z) * (b.z + bb.z)
            + (a.w + bb.w) * (b.w + bb.w);

    p += __shfl_xor_sync(0xFFFFFFFFu, p, 1);
    p += __shfl_xor_sync(0xFFFFFFFFu, p, 2);
    p += __shfl_xor_sync(0xFFFFFFFFu, p, 4);

    if (active && c == 0) out[e] = p;
}

// ---------------------------------------------------------------------------
extern "C" void kernel_launch(void* const* d_in, const int* in_sizes, int n_in,
                              void* d_out, int out_size)
{
    const float* x         = (const float*)d_in[0];
    const int*   adj_src   = (const int*)  d_in[1];
    const int*   adj_dst   = (const int*)  d_in[2];
    const float* adj_val   = (const float*)d_in[3];
    const int*   edge_idx  = (const int*)  d_in[4];
    const float* W1        = (const float*)d_in[5];
    const float* b1        = (const float*)d_in[6];
    const float* W2        = (const float*)d_in[7];
    const float* b2        = (const float*)d_in[8];
    float*       out       = (float*)d_out;

    int n   = in_sizes[0] / D_IN;
    int nnz = in_sizes[3];
    int ne  = in_sizes[4] / 2;
    (void)n_in; (void)out_size;

    // GEMM1 (TF32 + cp.async, fused S1/S2 zeroing)
    cudaFuncSetAttribute(gemm1_tf32_v3,
                         cudaFuncAttributeMaxDynamicSharedMemorySize, GEMM1_SMEM);
    gemm1_tf32_v3<<<(n + 127) / 128, 256, GEMM1_SMEM>>>(x, W1, n);
    // SpMM1 (d=64)
    {
        long long total = (long long)nnz * 16;
        int blocks = (int)((total + 255) / 256);
        spmm64_kernel<<<blocks, 256>>>(adj_src, adj_dst, adj_val, nnz);
    }
    // GEMM2 (fused relu + b1)
    gemm2_kernel<<<(n + 63) / 64, 256>>>(b1, W2, n);
    // SpMM2 (d=32)
    {
        long long total = (long long)nnz * 8;
        int blocks = (int)((total + 255) / 256);
        spmm32_kernel<<<blocks, 256>>>(adj_src, adj_dst, adj_val, nnz);
    }
    // Decoder
    {
        long long total = (long long)ne * 8;
        int blocks = (int)((total + 255) / 256);
        decoder_kernel<<<blocks, 256>>>(edge_idx, b2, out, ne);
    }
}

// round 6
// speedup vs baseline: 1.6302x; 1.2821x over previous
#include <cuda_runtime.h>
#include <stdint.h>

#define D_IN   256
#define D_HID  64
#define D_EMB  32
#define MAX_NODES 100000

// Scratch (static __device__ — no allocation allowed)
__device__ float g_H [MAX_NODES * D_HID];   // x @ W1
__device__ float g_S1[MAX_NODES * D_HID];   // A @ H
__device__ float g_Z1[MAX_NODES * D_EMB];   // relu(S1+b1) @ W2
__device__ float g_S2[MAX_NODES * D_EMB];   // A @ Z1

// ---------------------------------------------------------------------------
// TF32 helpers
// ---------------------------------------------------------------------------
__device__ __forceinline__ unsigned f2tf32(float f) {
    unsigned r;
    asm("cvt.rna.tf32.f32 %0, %1;" : "=r"(r) : "f"(f));
    return r;
}
__device__ __forceinline__ unsigned bits2tf32(unsigned b) {
    unsigned r;
    asm("cvt.rna.tf32.f32 %0, %1;" : "=r"(r) : "r"(b));
    return r;
}

__device__ __forceinline__ void mma_tf32(
    float& d0, float& d1, float& d2, float& d3,
    unsigned a0, unsigned a1, unsigned a2, unsigned a3,
    unsigned b0, unsigned b1)
{
    asm volatile(
        "mma.sync.aligned.m16n8k8.row.col.f32.tf32.tf32.f32 "
        "{%0,%1,%2,%3}, {%4,%5,%6,%7}, {%8,%9}, {%0,%1,%2,%3};"
        : "+f"(d0), "+f"(d1), "+f"(d2), "+f"(d3)
        : "r"(a0), "r"(a1), "r"(a2), "r"(a3), "r"(b0), "r"(b1));
}

__device__ __forceinline__ void cp_async16(unsigned smem_addr, const void* gptr) {
    asm volatile("cp.async.cg.shared.global [%0], [%1], 16;"
                 :: "r"(smem_addr), "l"(gptr));
}

// ---------------------------------------------------------------------------
// GEMM1 (TF32 + cp.async double buffer + fused zeroing + rna-cvt on A frags)
//   H = x @ W1   [n,256] @ [256,64]
// ---------------------------------------------------------------------------
#define W_STRIDE 72
#define X_STRIDE 36
#define W_WORDS  (256 * W_STRIDE)
#define X_WORDS  (128 * X_STRIDE)
#define GEMM1_SMEM ((W_WORDS + 2 * X_WORDS) * 4)

__global__ __launch_bounds__(256) void gemm1_tf32_v3(
    const float* __restrict__ x, const float* __restrict__ W1, int n)
{
    extern __shared__ unsigned smem[];
    unsigned* Wsh = smem;                       // [256][72]
    float*    xsf = (float*)(smem + W_WORDS);   // [2][128][36]

    int tid  = threadIdx.x;
    int warp = tid >> 5;
    int lane = tid & 31;
    int row_base = blockIdx.x * 128;
    int wm   = warp * 16;
    int qrow = lane >> 2;
    int qcol = lane & 3;

    unsigned xs_base;
    asm("{ .reg .u64 t; cvta.to.shared.u64 t, %1; cvt.u32.u64 %0, t; }"
        : "=r"(xs_base) : "l"(xsf));

    // prefetch x chunk 0 into buffer 0
    #pragma unroll
    for (int l = 0; l < 4; l++) {
        int flat = tid + l * 256;
        int r    = flat >> 3;
        int c4   = flat & 7;
        int grow = row_base + r; if (grow >= n) grow = n - 1;
        cp_async16(xs_base + (unsigned)(r * X_STRIDE + c4 * 4) * 4,
                   x + (size_t)grow * D_IN + c4 * 4);
    }
    asm volatile("cp.async.commit_group;");

    // stage whole W1 (tf32, rna)
    #pragma unroll
    for (int l = 0; l < 16; l++) {
        int flat = tid + l * 256;
        int k  = flat >> 4;
        int cc = (flat & 15) * 4;
        float4 w = __ldg((const float4*)(W1 + (size_t)k * 64 + cc));
        Wsh[k * W_STRIDE + cc + 0] = f2tf32(w.x);
        Wsh[k * W_STRIDE + cc + 1] = f2tf32(w.y);
        Wsh[k * W_STRIDE + cc + 2] = f2tf32(w.z);
        Wsh[k * W_STRIDE + cc + 3] = f2tf32(w.w);
    }

    // fused zeroing of S1 / S2
    {
        int gtid = blockIdx.x * 256 + tid;
        int nthr = gridDim.x * 256;
        float4 z = make_float4(0.f, 0.f, 0.f, 0.f);
        for (int i = gtid; i < n * 16; i += nthr) ((float4*)g_S1)[i] = z;
        for (int i = gtid; i < n * 8;  i += nthr) ((float4*)g_S2)[i] = z;
    }

    float c[8][4];
    #pragma unroll
    for (int nt = 0; nt < 8; nt++)
        #pragma unroll
        for (int i = 0; i < 4; i++) c[nt][i] = 0.f;

    #pragma unroll
    for (int kc = 0; kc < 8; kc++) {
        if (kc + 1 < 8) {
            int buf = (kc + 1) & 1;
            #pragma unroll
            for (int l = 0; l < 4; l++) {
                int flat = tid + l * 256;
                int r    = flat >> 3;
                int c4   = flat & 7;
                int grow = row_base + r; if (grow >= n) grow = n - 1;
                cp_async16(xs_base + (unsigned)(buf * X_WORDS + r * X_STRIDE + c4 * 4) * 4,
                           x + (size_t)grow * D_IN + (kc + 1) * 32 + c4 * 4);
            }
            asm volatile("cp.async.commit_group;");
            asm volatile("cp.async.wait_group 1;");
        } else {
            asm volatile("cp.async.wait_group 0;");
        }
        __syncthreads();

        const unsigned* xb = (const unsigned*)(xsf + (kc & 1) * X_WORDS);
        #pragma unroll
        for (int k8 = 0; k8 < 4; k8++) {
            int ar = wm + qrow;
            int ac = k8 * 8 + qcol;
            unsigned a0 = bits2tf32(xb[(ar    ) * X_STRIDE + ac    ]);
            unsigned a1 = bits2tf32(xb[(ar + 8) * X_STRIDE + ac    ]);
            unsigned a2 = bits2tf32(xb[(ar    ) * X_STRIDE + ac + 4]);
            unsigned a3 = bits2tf32(xb[(ar + 8) * X_STRIDE + ac + 4]);
            int kg = kc * 32 + k8 * 8 + qcol;
            #pragma unroll
            for (int nt = 0; nt < 8; nt++) {
                unsigned b0 = Wsh[(kg    ) * W_STRIDE + nt * 8 + qrow];
                unsigned b1 = Wsh[(kg + 4) * W_STRIDE + nt * 8 + qrow];
                mma_tf32(c[nt][0], c[nt][1], c[nt][2], c[nt][3],
                         a0, a1, a2, a3, b0, b1);
            }
        }
        __syncthreads();
    }

    int r0 = row_base + wm + qrow;
    int cb = qcol * 2;
    #pragma unroll
    for (int nt = 0; nt < 8; nt++) {
        if (r0 < n)
            *(float2*)(g_H + (size_t)r0 * D_HID + nt*8 + cb) =
                make_float2(c[nt][0], c[nt][1]);
        if (r0 + 8 < n)
            *(float2*)(g_H + (size_t)(r0 + 8) * D_HID + nt*8 + cb) =
                make_float2(c[nt][2], c[nt][3]);
    }
}

// ---------------------------------------------------------------------------
// red.v4 helper
// ---------------------------------------------------------------------------
__device__ __forceinline__ void red_add_v4(float* p, float4 v) {
    asm volatile("red.global.add.v4.f32 [%0], {%1,%2,%3,%4};"
                 :: "l"(p), "f"(v.x), "f"(v.y), "f"(v.z), "f"(v.w)
                 : "memory");
}

// ---------------------------------------------------------------------------
// SpMM d=64: 16 lanes per edge, 4 edges per thread (MLP=4).
// ---------------------------------------------------------------------------
__global__ __launch_bounds__(256) void spmm64_kernel(
    const int* __restrict__ src, const int* __restrict__ dst,
    const float* __restrict__ val, int nnz)
{
    int t = blockIdx.x * blockDim.x + threadIdx.x;
    int c = t & 15;
    int base = (t >> 4) * 4;
    if (base >= nnz) return;

    int   s[4], d[4];
    float v[4];
    #pragma unroll
    for (int j = 0; j < 4; j++) {
        int e = base + j;
        bool ok = (e < nnz);
        int ec = ok ? e : base;
        s[j] = __ldg(src + ec);
        d[j] = __ldg(dst + ec);
        v[j] = ok ? __ldg(val + ec) : 0.f;
    }
    float4 h[4];
    #pragma unroll
    for (int j = 0; j < 4; j++)
        h[j] = __ldg((const float4*)(g_H + (size_t)s[j] * D_HID) + c);
    #pragma unroll
    for (int j = 0; j < 4; j++)
        red_add_v4(g_S1 + (size_t)d[j] * D_HID + c * 4,
                   make_float4(v[j]*h[j].x, v[j]*h[j].y, v[j]*h[j].z, v[j]*h[j].w));
}

// ---------------------------------------------------------------------------
// GEMM2: Z1 = relu(S1 + b1) @ W2   [n,64] @ [64,32]
// ---------------------------------------------------------------------------
__global__ __launch_bounds__(256) void gemm2_kernel(
    const float* __restrict__ b1, const float* __restrict__ W2, int n)
{
    __shared__ float zs[64][65];
    __shared__ float ws[64][32];

    int tid = threadIdx.x;
    int row_base = blockIdx.x * 64;

    #pragma unroll
    for (int l = 0; l < 4; l++) {
        int flat = tid + l * 256;
        int r  = flat >> 4;
        int c4 = flat & 15;
        float4 v = make_float4(0.f,0.f,0.f,0.f);
        if (row_base + r < n)
            v = *(const float4*)(g_S1 + (size_t)row_base * D_HID + (size_t)flat * 4);
        float4 bb = __ldg((const float4*)b1 + c4);
        v.x = fmaxf(v.x + bb.x, 0.f);
        v.y = fmaxf(v.y + bb.y, 0.f);
        v.z = fmaxf(v.z + bb.z, 0.f);
        v.w = fmaxf(v.w + bb.w, 0.f);
        zs[r][c4*4+0] = v.x; zs[r][c4*4+1] = v.y;
        zs[r][c4*4+2] = v.z; zs[r][c4*4+3] = v.w;
    }
    #pragma unroll
    for (int l = 0; l < 2; l++) {
        int flat = tid + l * 256;
        ((float4*)&ws[0][0])[flat] = __ldg((const float4*)W2 + flat);
    }
    __syncthreads();

    int ty = tid >> 3;
    int tx = tid & 7;
    int col = tx * 4;

    float a00=0,a01=0,a02=0,a03=0;
    float a10=0,a11=0,a12=0,a13=0;

    #pragma unroll 16
    for (int kk = 0; kk < 64; kk++) {
        float z0 = zs[ty*2+0][kk];
        float z1 = zs[ty*2+1][kk];
        float4 b = *(float4*)&ws[kk][col];
        a00 += z0*b.x; a01 += z0*b.y; a02 += z0*b.z; a03 += z0*b.w;
        a10 += z1*b.x; a11 += z1*b.y; a12 += z1*b.z; a13 += z1*b.w;
    }

    int r0 = row_base + ty*2;
    if (r0 + 0 < n) *(float4*)(g_Z1 + (size_t)(r0+0)*D_EMB + col) = make_float4(a00,a01,a02,a03);
    if (r0 + 1 < n) *(float4*)(g_Z1 + (size_t)(r0+1)*D_EMB + col) = make_float4(a10,a11,a12,a13);
}

// ---------------------------------------------------------------------------
// SpMM d=32: 8 lanes per edge, 4 edges per thread (MLP=4).
// ---------------------------------------------------------------------------
__global__ __launch_bounds__(256) void spmm32_kernel(
    const int* __restrict__ src, const int* __restrict__ dst,
    const float* __restrict__ val, int nnz)
{
    int t = blockIdx.x * blockDim.x + threadIdx.x;
    int c = t & 7;
    int base = (t >> 3) * 4;
    if (base >= nnz) return;

    int   s[4], d[4];
    float v[4];
    #pragma unroll
    for (int j = 0; j < 4; j++) {
        int e = base + j;
        bool ok = (e < nnz);
        int ec = ok ? e : base;
        s[j] = __ldg(src + ec);
        d[j] = __ldg(dst + ec);
        v[j] = ok ? __ldg(val + ec) : 0.f;
    }
    float4 h[4];
    #pragma unroll
    for (int j = 0; j < 4; j++)
        h[j] = __ldg((const float4*)(g_Z1 + (size_t)s[j] * D_EMB) + c);
    #pragma unroll
    for (int j = 0; j < 4; j++)
        red_add_v4(g_S2 + (size_t)d[j] * D_EMB + c * 4,
                   make_float4(v[j]*h[j].x, v[j]*h[j].y, v[j]*h[j].z, v[j]*h[j].w));
}

// ---------------------------------------------------------------------------
// Decoder: 8 lanes per edge, 2 edges per thread (MLP=4 gathers).
// ---------------------------------------------------------------------------
__global__ __launch_bounds__(256) void decoder_kernel(
    const int* __restrict__ edge_index, const float* __restrict__ b2,
    float* __restrict__ out, int ne)
{
    int t = blockIdx.x * blockDim.x + threadIdx.x;
    int c = t & 7;
    int base = (t >> 3) * 2;
    if (base >= ne) return;

    int e0 = base;
    int e1 = (base + 1 < ne) ? base + 1 : base;

    int s0 = __ldg(edge_index + e0);
    int d0 = __ldg(edge_index + ne + e0);
    int s1 = __ldg(edge_index + e1);
    int d1 = __ldg(edge_index + ne + e1);

    float4 bb = __ldg((const float4*)b2 + c);
    float4 a0 = __ldg((const float4*)(g_S2 + (size_t)s0 * D_EMB) + c);
    float4 b0 = __ldg((const float4*)(g_S2 + (size_t)d0 * D_EMB) + c);
    float4 a1 = __ldg((const float4*)(g_S2 + (size_t)s1 * D_EMB) + c);
    float4 b1 = __ldg((const float4*)(g_S2 + (size_t)d1 * D_EMB) + c);

    float p0 = (a0.x + bb.x) * (b0.x + bb.x)
             + (a0.y + bb.y) * (b0.y + bb.y)
             + (a0.z + bb.z) * (b0.z + bb.z)
             + (a0.w + bb.w) * (b0.w + bb.w);
    float p1 = (a1.x + bb.x) * (b1.x + bb.x)
             + (a1.y + bb.y) * (b1.y + bb.y)
             + (a1.z + bb.z) * (b1.z + bb.z)
             + (a1.w + bb.w) * (b1.w + bb.w);

    #pragma unroll
    for (int m = 1; m < 8; m <<= 1) {
        p0 += __shfl_xor_sync(0xFFFFFFFFu, p0, m);
        p1 += __shfl_xor_sync(0xFFFFFFFFu, p1, m);
    }

    if (c == 0) {
        out[e0] = p0;
        if (base + 1 < ne) out[base + 1] = p1;
    }
}

// ---------------------------------------------------------------------------
extern "C" void kernel_launch(void* const* d_in, const int* in_sizes, int n_in,
                              void* d_out, int out_size)
{
    const float* x         = (const float*)d_in[0];
    const int*   adj_src   = (const int*)  d_in[1];
    const int*   adj_dst   = (const int*)  d_in[2];
    const float* adj_val   = (const float*)d_in[3];
    const int*   edge_idx  = (const int*)  d_in[4];
    const float* W1        = (const float*)d_in[5];
    const float* b1        = (const float*)d_in[6];
    const float* W2        = (const float*)d_in[7];
    const float* b2        = (const float*)d_in[8];
    float*       out       = (float*)d_out;

    int n   = in_sizes[0] / D_IN;
    int nnz = in_sizes[3];
    int ne  = in_sizes[4] / 2;
    (void)n_in; (void)out_size;

    // GEMM1 (TF32 + cp.async, fused S1/S2 zeroing)
    cudaFuncSetAttribute(gemm1_tf32_v3,
                         cudaFuncAttributeMaxDynamicSharedMemorySize, GEMM1_SMEM);
    gemm1_tf32_v3<<<(n + 127) / 128, 256, GEMM1_SMEM>>>(x, W1, n);
    // SpMM1 (d=64), 4 edges per 16-lane group
    {
        long long groups = ((long long)nnz + 3) / 4;
        long long total  = groups * 16;
        int blocks = (int)((total + 255) / 256);
        spmm64_kernel<<<blocks, 256>>>(adj_src, adj_dst, adj_val, nnz);
    }
    // GEMM2 (fused relu + b1)
    gemm2_kernel<<<(n + 63) / 64, 256>>>(b1, W2, n);
    // SpMM2 (d=32), 4 edges per 8-lane group
    {
        long long groups = ((long long)nnz + 3) / 4;
        long long total  = groups * 8;
        int blocks = (int)((total + 255) / 256);
        spmm32_kernel<<<blocks, 256>>>(adj_src, adj_dst, adj_val, nnz);
    }
    // Decoder, 2 edges per 8-lane group
    {
        long long groups = ((long long)ne + 1) / 2;
        long long total  = groups * 8;
        int blocks = (int)((total + 255) / 256);
        decoder_kernel<<<blocks, 256>>>(edge_idx, b2, out, ne);
    }
}